// round 5
// baseline (speedup 1.0000x reference)
#include <cuda_runtime.h>

#define N_NODE 100000
#define EMB    112
#define NNZ    1000000
#define BATCH  512
#define SEQL   50
#define MAXNEED (BATCH * SEQL)

#define SCAN_BLK 512
#define SCAN_NB  ((N_NODE + SCAN_BLK - 1) / SCAN_BLK)   // 196

// ---------------- scratch (device globals; no allocations allowed) ----------
__device__ int   g_cnt[N_NODE];
__device__ int   g_row_ptr[N_NODE + 1];
__device__ int   g_row_fill[N_NODE];
__device__ int   g_blocksum[SCAN_NB];
__device__ int   g_need[MAXNEED];                  // row index or -1 (dups OK)
__device__ uint2 g_csr[NNZ];                       // interleaved {val, col}
__device__ float g_buf1[(size_t)N_NODE * EMB];
__device__ float g_buf2[(size_t)N_NODE * EMB];
__device__ float g_sess[BATCH * EMB];
__device__ float g_tmp[BATCH * EMB];
__device__ float g_accum[BATCH * EMB];
__device__ float g_DA[BATCH * BATCH];

// ---------------- init: zero counts + build need list (no dedup) -------------
__global__ void k_init(const int* __restrict__ items) {
    int i = blockIdx.x * blockDim.x + threadIdx.x;
    if (i < N_NODE) g_cnt[i] = 0;
    if (i < MAXNEED) {
        int it = items[i];
        g_need[i] = it - 1;                        // -1 when pad (it==0)
    }
}

__global__ void k_count(const int* __restrict__ rows) {
    int i = blockIdx.x * blockDim.x + threadIdx.x;
    if (i < NNZ) atomicAdd(&g_cnt[rows[i]], 1);
}

// ---------------- 3-phase grid-wide exclusive scan ----------------------------
__global__ void k_scan1() {
    __shared__ int ws[SCAN_BLK / 32];
    const int tid  = threadIdx.x;
    const int lane = tid & 31;
    const int wid  = tid >> 5;
    const int i    = blockIdx.x * SCAN_BLK + tid;

    int v = (i < N_NODE) ? g_cnt[i] : 0;
    int inc = v;
    #pragma unroll
    for (int off = 1; off < 32; off <<= 1) {
        int t = __shfl_up_sync(0xffffffffu, inc, off);
        if (lane >= off) inc += t;
    }
    if (lane == 31) ws[wid] = inc;
    __syncthreads();
    if (wid == 0) {
        int s = (lane < SCAN_BLK / 32) ? ws[lane] : 0;
        #pragma unroll
        for (int off = 1; off < SCAN_BLK / 32; off <<= 1) {
            int t = __shfl_up_sync(0xffffffffu, s, off);
            if (lane >= off) s += t;
        }
        if (lane < SCAN_BLK / 32) ws[lane] = s;
    }
    __syncthreads();

    int excl = inc - v + (wid > 0 ? ws[wid - 1] : 0);
    if (i < N_NODE) g_row_ptr[i] = excl;
    if (tid == SCAN_BLK - 1) g_blocksum[blockIdx.x] = excl + v;
}

__global__ void k_scan2() {
    __shared__ int ws[8];
    const int tid  = threadIdx.x;
    const int lane = tid & 31;
    const int wid  = tid >> 5;

    int v = (tid < SCAN_NB) ? g_blocksum[tid] : 0;
    int inc = v;
    #pragma unroll
    for (int off = 1; off < 32; off <<= 1) {
        int t = __shfl_up_sync(0xffffffffu, inc, off);
        if (lane >= off) inc += t;
    }
    if (lane == 31) ws[wid] = inc;
    __syncthreads();
    if (wid == 0) {
        int s = (lane < 8) ? ws[lane] : 0;
        #pragma unroll
        for (int off = 1; off < 8; off <<= 1) {
            int t = __shfl_up_sync(0xffffffffu, s, off);
            if (lane >= off) s += t;
        }
        if (lane < 8) ws[lane] = s;
    }
    __syncthreads();

    int excl = inc - v + (wid > 0 ? ws[wid - 1] : 0);
    if (tid < SCAN_NB) g_blocksum[tid] = excl;
    if (tid == SCAN_NB - 1) g_row_ptr[N_NODE] = excl + v;
}

__global__ void k_scan3() {
    int i = blockIdx.x * blockDim.x + threadIdx.x;
    if (i < N_NODE) {
        int p = g_row_ptr[i] + g_blocksum[i / SCAN_BLK];
        g_row_ptr[i]  = p;
        g_row_fill[i] = p;
    }
}

__global__ void k_scatter(const float* __restrict__ vals,
                          const int* __restrict__ rows,
                          const int* __restrict__ cols) {
    int i = blockIdx.x * blockDim.x + threadIdx.x;
    if (i < NNZ) {
        int pos = atomicAdd(&g_row_fill[rows[i]], 1);
        g_csr[pos] = make_uint2(__float_as_uint(vals[i]), (unsigned)cols[i]);
    }
}

// ---------------- SpMM core: warp per row, depth-4 pipeline -------------------
__device__ __forceinline__ void spmm_row(int row, const float* __restrict__ x,
                                         float* __restrict__ y, int lane) {
    int s = g_row_ptr[row];
    int e = g_row_ptr[row + 1];
    bool act = lane < (EMB / 4);                  // 28 active lanes
    float4 acc = make_float4(0.f, 0.f, 0.f, 0.f);

    int k = s;
    for (; k + 3 < e; k += 4) {
        uint2 m0 = g_csr[k];
        uint2 m1 = g_csr[k + 1];
        uint2 m2 = g_csr[k + 2];
        uint2 m3 = g_csr[k + 3];
        if (act) {
            float4 a = *reinterpret_cast<const float4*>(x + (size_t)m0.y * EMB + lane * 4);
            float4 b = *reinterpret_cast<const float4*>(x + (size_t)m1.y * EMB + lane * 4);
            float4 c = *reinterpret_cast<const float4*>(x + (size_t)m2.y * EMB + lane * 4);
            float4 d = *reinterpret_cast<const float4*>(x + (size_t)m3.y * EMB + lane * 4);
            float v0 = __uint_as_float(m0.x), v1 = __uint_as_float(m1.x);
            float v2 = __uint_as_float(m2.x), v3 = __uint_as_float(m3.x);
            acc.x += v0 * a.x + v1 * b.x + v2 * c.x + v3 * d.x;
            acc.y += v0 * a.y + v1 * b.y + v2 * c.y + v3 * d.y;
            acc.z += v0 * a.z + v1 * b.z + v2 * c.z + v3 * d.z;
            acc.w += v0 * a.w + v1 * b.w + v2 * c.w + v3 * d.w;
        }
    }
    for (; k < e; k++) {
        uint2 m = g_csr[k];
        if (act) {
            float4 a = *reinterpret_cast<const float4*>(x + (size_t)m.y * EMB + lane * 4);
            float v = __uint_as_float(m.x);
            acc.x += v * a.x; acc.y += v * a.y; acc.z += v * a.z; acc.w += v * a.w;
        }
    }
    if (act)
        *reinterpret_cast<float4*>(y + (size_t)row * EMB + lane * 4) = acc;
}

__global__ void k_spmm1(const float* __restrict__ emb) {
    int warp = (blockIdx.x * blockDim.x + threadIdx.x) >> 5;
    int lane = threadIdx.x & 31;
    if (warp >= N_NODE) return;
    spmm_row(warp, emb, g_buf1, lane);
}

__global__ void k_spmm2() {
    int widx = (blockIdx.x * blockDim.x + threadIdx.x) >> 5;
    int lane = threadIdx.x & 31;
    if (widx >= MAXNEED) return;
    int row = g_need[widx];
    if (row < 0) return;
    spmm_row(row, g_buf1, g_buf2, lane);          // dup rows write identical data
}

// ---------------- session pooling ---------------------------------------------
__global__ void k_pool(const float* __restrict__ emb,
                       const int* __restrict__ items,
                       const float* __restrict__ slen) {
    int b = blockIdx.x;
    int c = threadIdx.x;                          // 112 threads
    float acc = 0.f;
    #pragma unroll 5
    for (int l = 0; l < SEQL; l++) {
        int it = items[b * SEQL + l];
        if (it > 0) {
            size_t o = (size_t)(it - 1) * EMB + c;
            acc += emb[o] + g_buf1[o] + g_buf2[o];
        }
    }
    float v = acc * (1.0f / 3.0f) / slen[b];
    g_sess[b * EMB + c]  = v;
    g_accum[b * EMB + c] = v;
}

// ---------------- DA = D @ A ---------------------------------------------------
__global__ void k_mm512(const float* __restrict__ D, const float* __restrict__ A) {
    __shared__ float sD[32][33];
    __shared__ float sA[32][33];
    int tx = threadIdx.x, ty = threadIdx.y;
    int row = blockIdx.y * 32 + ty;
    int col = blockIdx.x * 32 + tx;
    float acc = 0.f;
    for (int k0 = 0; k0 < 512; k0 += 32) {
        sD[ty][tx] = D[row * 512 + k0 + tx];
        sA[ty][tx] = A[(k0 + ty) * 512 + col];
        __syncthreads();
        #pragma unroll
        for (int k = 0; k < 32; k++) acc += sD[ty][k] * sA[k][tx];
        __syncthreads();
    }
    g_DA[row * 512 + col] = acc;
}

// ---------------- tmp = sess @ W^T ---------------------------------------------
__global__ void k_linear(const float* __restrict__ w) {
    __shared__ float s[EMB];
    int b = blockIdx.x;
    int o = threadIdx.x;                          // 112 threads
    s[o] = g_sess[b * EMB + o];
    __syncthreads();
    float acc = 0.f;
    #pragma unroll 8
    for (int k = 0; k < EMB; k++) acc += s[k] * w[o * EMB + k];
    g_tmp[b * EMB + o] = acc;
}

// ---------------- tiled: S = l2norm_rows(DA @ tmp); accum/out -------------------
// grid = 16 blocks (32 batch rows each), block = (32, 32); warp ty owns row ty.
__global__ void k_danorm(int last, float* __restrict__ out) {
    __shared__ float sDA[32][33];
    __shared__ float sT[32][112];
    const int tx = threadIdx.x, ty = threadIdx.y;
    const int row = blockIdx.x * 32 + ty;
    const int tid = ty * 32 + tx;

    float a0 = 0.f, a1 = 0.f, a2 = 0.f, a3 = 0.f;

    for (int k0 = 0; k0 < 512; k0 += 32) {
        sDA[ty][tx] = g_DA[row * 512 + k0 + tx];
        #pragma unroll
        for (int e = tid; e < 32 * EMB; e += 1024)
            sT[e / EMB][e % EMB] = g_tmp[(size_t)(k0 + e / EMB) * EMB + (e % EMB)];
        __syncthreads();
        #pragma unroll
        for (int kk = 0; kk < 32; kk++) {
            float d = sDA[ty][kk];
            a0 += d * sT[kk][tx];
            a1 += d * sT[kk][tx + 32];
            a2 += d * sT[kk][tx + 64];
            if (tx < 16) a3 += d * sT[kk][tx + 96];
        }
        __syncthreads();
    }

    // row L2-norm via warp shuffle (warp ty == row)
    float ss = a0 * a0 + a1 * a1 + a2 * a2 + ((tx < 16) ? a3 * a3 : 0.f);
    #pragma unroll
    for (int off = 16; off > 0; off >>= 1)
        ss += __shfl_xor_sync(0xffffffffu, ss, off);
    float inv = 1.0f / fmaxf(sqrtf(ss), 1e-12f);

    const int base = row * EMB;
    if (last) {
        out[base + tx]      = (g_accum[base + tx]      + a0 * inv) * (1.0f / 3.0f);
        out[base + tx + 32] = (g_accum[base + tx + 32] + a1 * inv) * (1.0f / 3.0f);
        out[base + tx + 64] = (g_accum[base + tx + 64] + a2 * inv) * (1.0f / 3.0f);
        if (tx < 16)
            out[base + tx + 96] = (g_accum[base + tx + 96] + a3 * inv) * (1.0f / 3.0f);
    } else {
        g_sess[base + tx]      = a0 * inv;  g_accum[base + tx]      += a0 * inv;
        g_sess[base + tx + 32] = a1 * inv;  g_accum[base + tx + 32] += a1 * inv;
        g_sess[base + tx + 64] = a2 * inv;  g_accum[base + tx + 64] += a2 * inv;
        if (tx < 16) {
            g_sess[base + tx + 96] = a3 * inv;
            g_accum[base + tx + 96] += a3 * inv;
        }
    }
}

// ---------------- launch --------------------------------------------------------
extern "C" void kernel_launch(void* const* d_in, const int* in_sizes, int n_in,
                              void* d_out, int out_size) {
    const float* emb   = (const float*)d_in[0];
    const float* vals  = (const float*)d_in[1];
    const int*   rows  = (const int*)d_in[2];
    const int*   cols  = (const int*)d_in[3];
    const float* D     = (const float*)d_in[4];
    const float* A     = (const float*)d_in[5];
    const int*   items = (const int*)d_in[6];
    const float* slen  = (const float*)d_in[7];
    const float* wsess = (const float*)d_in[8];
    float* out = (float*)d_out;

    (void)in_sizes; (void)n_in; (void)out_size;

    // CSR build + need list
    k_init<<<(N_NODE + 255) / 256, 256>>>(items);
    k_count<<<(NNZ + 255) / 256, 256>>>(rows);
    k_scan1<<<SCAN_NB, SCAN_BLK>>>();
    k_scan2<<<1, 256>>>();
    k_scan3<<<(N_NODE + 255) / 256, 256>>>();
    k_scatter<<<(NNZ + 255) / 256, 256>>>(vals, rows, cols);

    // hyperconv
    const int spmm1_blocks = (N_NODE * 32 + 255) / 256;
    k_spmm1<<<spmm1_blocks, 256>>>(emb);
    const int spmm2_blocks = (MAXNEED * 32 + 255) / 256;
    k_spmm2<<<spmm2_blocks, 256>>>();

    // sessconv
    k_pool<<<BATCH, EMB>>>(emb, items, slen);
    k_mm512<<<dim3(16, 16), dim3(32, 32)>>>(D, A);

    k_linear<<<BATCH, EMB>>>(wsess + 0 * EMB * EMB);
    k_danorm<<<16, dim3(32, 32)>>>(0, out);
    k_linear<<<BATCH, EMB>>>(wsess + 1 * EMB * EMB);
    k_danorm<<<16, dim3(32, 32)>>>(1, out);
}

// round 6
// speedup vs baseline: 1.3119x; 1.3119x over previous
#include <cuda_runtime.h>

#define N_NODE 100000
#define EMB    112
#define NNZ    1000000
#define BATCH  512
#define SEQL   50
#define MAXNEED (BATCH * SEQL)

#define SCAN_BLK 512
#define SCAN_NB  ((N_NODE + SCAN_BLK - 1) / SCAN_BLK)   // 196

// ---------------- scratch (device globals; no allocations allowed) ----------
__device__ int   g_cnt[N_NODE];
__device__ int   g_row_ptr[N_NODE + 1];
__device__ int   g_row_fill[N_NODE];
__device__ int   g_blocksum[SCAN_NB];
__device__ int   g_flag[N_NODE];
__device__ int   g_need[MAXNEED];
__device__ int   g_nneed;
__device__ uint2 g_csr[NNZ];                       // interleaved {val, col}
__device__ float g_buf1[(size_t)N_NODE * EMB];
__device__ float g_buf2[(size_t)N_NODE * EMB];
__device__ float g_sess[BATCH * EMB];
__device__ float g_tmp[BATCH * EMB];
__device__ float g_accum[BATCH * EMB];
__device__ float g_DA[BATCH * BATCH];

// ---------------- init: zero counters + flags --------------------------------
__global__ void k_zero() {
    int i = blockIdx.x * blockDim.x + threadIdx.x;
    if (i < N_NODE) { g_cnt[i] = 0; g_flag[i] = 0; }
    if (i == 0)     g_nneed = 0;
}

__global__ void k_mark(const int* __restrict__ items) {
    int i = blockIdx.x * blockDim.x + threadIdx.x;
    if (i < BATCH * SEQL) {
        int it = items[i];
        if (it > 0) g_flag[it - 1] = 1;
    }
}

__global__ void k_count(const int* __restrict__ rows) {
    int i = blockIdx.x * blockDim.x + threadIdx.x;
    if (i < NNZ) atomicAdd(&g_cnt[rows[i]], 1);
}

// ---------------- 3-phase grid-wide exclusive scan ----------------------------
__global__ void k_scan1() {
    __shared__ int ws[SCAN_BLK / 32];
    const int tid  = threadIdx.x;
    const int lane = tid & 31;
    const int wid  = tid >> 5;
    const int i    = blockIdx.x * SCAN_BLK + tid;

    int v = (i < N_NODE) ? g_cnt[i] : 0;
    int inc = v;
    #pragma unroll
    for (int off = 1; off < 32; off <<= 1) {
        int t = __shfl_up_sync(0xffffffffu, inc, off);
        if (lane >= off) inc += t;
    }
    if (lane == 31) ws[wid] = inc;
    __syncthreads();
    if (wid == 0) {
        int s = (lane < SCAN_BLK / 32) ? ws[lane] : 0;
        #pragma unroll
        for (int off = 1; off < SCAN_BLK / 32; off <<= 1) {
            int t = __shfl_up_sync(0xffffffffu, s, off);
            if (lane >= off) s += t;
        }
        if (lane < SCAN_BLK / 32) ws[lane] = s;
    }
    __syncthreads();

    int excl = inc - v + (wid > 0 ? ws[wid - 1] : 0);
    if (i < N_NODE) g_row_ptr[i] = excl;
    if (tid == SCAN_BLK - 1) g_blocksum[blockIdx.x] = excl + v;
}

__global__ void k_scan2() {
    __shared__ int ws[8];
    const int tid  = threadIdx.x;
    const int lane = tid & 31;
    const int wid  = tid >> 5;

    int v = (tid < SCAN_NB) ? g_blocksum[tid] : 0;
    int inc = v;
    #pragma unroll
    for (int off = 1; off < 32; off <<= 1) {
        int t = __shfl_up_sync(0xffffffffu, inc, off);
        if (lane >= off) inc += t;
    }
    if (lane == 31) ws[wid] = inc;
    __syncthreads();
    if (wid == 0) {
        int s = (lane < 8) ? ws[lane] : 0;
        #pragma unroll
        for (int off = 1; off < 8; off <<= 1) {
            int t = __shfl_up_sync(0xffffffffu, s, off);
            if (lane >= off) s += t;
        }
        if (lane < 8) ws[lane] = s;
    }
    __syncthreads();

    int excl = inc - v + (wid > 0 ? ws[wid - 1] : 0);
    if (tid < SCAN_NB) g_blocksum[tid] = excl;
    if (tid == SCAN_NB - 1) g_row_ptr[N_NODE] = excl + v;
}

// phase 3: propagate block offsets; also compact needed-row list (flags ready)
__global__ void k_scan3() {
    int i = blockIdx.x * blockDim.x + threadIdx.x;
    if (i < N_NODE) {
        int p = g_row_ptr[i] + g_blocksum[i / SCAN_BLK];
        g_row_ptr[i]  = p;
        g_row_fill[i] = p;
        if (g_flag[i]) {
            int q = atomicAdd(&g_nneed, 1);
            g_need[q] = i;
        }
    }
}

__global__ void k_scatter(const float* __restrict__ vals,
                          const int* __restrict__ rows,
                          const int* __restrict__ cols) {
    int i = blockIdx.x * blockDim.x + threadIdx.x;
    if (i < NNZ) {
        int pos = atomicAdd(&g_row_fill[rows[i]], 1);
        g_csr[pos] = make_uint2(__float_as_uint(vals[i]), (unsigned)cols[i]);
    }
}

// ---------------- SpMM core: warp per row, depth-4 pipeline -------------------
__device__ __forceinline__ void spmm_row(int row, const float* __restrict__ x,
                                         float* __restrict__ y, int lane) {
    int s = g_row_ptr[row];
    int e = g_row_ptr[row + 1];
    bool act = lane < (EMB / 4);                  // 28 active lanes
    float4 acc = make_float4(0.f, 0.f, 0.f, 0.f);

    int k = s;
    for (; k + 3 < e; k += 4) {
        uint2 m0 = g_csr[k];
        uint2 m1 = g_csr[k + 1];
        uint2 m2 = g_csr[k + 2];
        uint2 m3 = g_csr[k + 3];
        if (act) {
            float4 a = *reinterpret_cast<const float4*>(x + (size_t)m0.y * EMB + lane * 4);
            float4 b = *reinterpret_cast<const float4*>(x + (size_t)m1.y * EMB + lane * 4);
            float4 c = *reinterpret_cast<const float4*>(x + (size_t)m2.y * EMB + lane * 4);
            float4 d = *reinterpret_cast<const float4*>(x + (size_t)m3.y * EMB + lane * 4);
            float v0 = __uint_as_float(m0.x), v1 = __uint_as_float(m1.x);
            float v2 = __uint_as_float(m2.x), v3 = __uint_as_float(m3.x);
            acc.x += v0 * a.x + v1 * b.x + v2 * c.x + v3 * d.x;
            acc.y += v0 * a.y + v1 * b.y + v2 * c.y + v3 * d.y;
            acc.z += v0 * a.z + v1 * b.z + v2 * c.z + v3 * d.z;
            acc.w += v0 * a.w + v1 * b.w + v2 * c.w + v3 * d.w;
        }
    }
    for (; k < e; k++) {
        uint2 m = g_csr[k];
        if (act) {
            float4 a = *reinterpret_cast<const float4*>(x + (size_t)m.y * EMB + lane * 4);
            float v = __uint_as_float(m.x);
            acc.x += v * a.x; acc.y += v * a.y; acc.z += v * a.z; acc.w += v * a.w;
        }
    }
    if (act)
        *reinterpret_cast<float4*>(y + (size_t)row * EMB + lane * 4) = acc;
}

__global__ void k_spmm1(const float* __restrict__ emb) {
    int warp = (blockIdx.x * blockDim.x + threadIdx.x) >> 5;
    int lane = threadIdx.x & 31;
    if (warp >= N_NODE) return;
    spmm_row(warp, emb, g_buf1, lane);
}

__global__ void k_spmm2() {
    int widx = (blockIdx.x * blockDim.x + threadIdx.x) >> 5;
    int lane = threadIdx.x & 31;
    if (widx >= g_nneed) return;
    spmm_row(g_need[widx], g_buf1, g_buf2, lane);
}

// ---------------- session pooling ---------------------------------------------
__global__ void k_pool(const float* __restrict__ emb,
                       const int* __restrict__ items,
                       const float* __restrict__ slen) {
    int b = blockIdx.x;
    int c = threadIdx.x;                          // 112 threads
    float acc = 0.f;
    #pragma unroll 5
    for (int l = 0; l < SEQL; l++) {
        int it = items[b * SEQL + l];
        if (it > 0) {
            size_t o = (size_t)(it - 1) * EMB + c;
            acc += emb[o] + g_buf1[o] + g_buf2[o];
        }
    }
    float v = acc * (1.0f / 3.0f) / slen[b];
    g_sess[b * EMB + c]  = v;
    g_accum[b * EMB + c] = v;
}

// ---------------- DA = D @ A ---------------------------------------------------
__global__ void k_mm512(const float* __restrict__ D, const float* __restrict__ A) {
    __shared__ float sD[32][33];
    __shared__ float sA[32][33];
    int tx = threadIdx.x, ty = threadIdx.y;
    int row = blockIdx.y * 32 + ty;
    int col = blockIdx.x * 32 + tx;
    float acc = 0.f;
    for (int k0 = 0; k0 < 512; k0 += 32) {
        sD[ty][tx] = D[row * 512 + k0 + tx];
        sA[ty][tx] = A[(k0 + ty) * 512 + col];
        __syncthreads();
        #pragma unroll
        for (int k = 0; k < 32; k++) acc += sD[ty][k] * sA[k][tx];
        __syncthreads();
    }
    g_DA[row * 512 + col] = acc;
}

// ---------------- tmp = sess @ W^T ---------------------------------------------
__global__ void k_linear(const float* __restrict__ w) {
    __shared__ float s[EMB];
    int b = blockIdx.x;
    int o = threadIdx.x;                          // 112 threads
    s[o] = g_sess[b * EMB + o];
    __syncthreads();
    float acc = 0.f;
    #pragma unroll 8
    for (int k = 0; k < EMB; k++) acc += s[k] * w[o * EMB + k];
    g_tmp[b * EMB + o] = acc;
}

// ---------------- sess = l2norm(DA @ tmp); accum += ; optional final write -----
__global__ void k_danorm(int last, float* __restrict__ out) {
    int b = blockIdx.x;
    int c = threadIdx.x;                          // 128 threads, 112 active
    float acc = 0.f;
    if (c < EMB) {
        const float* __restrict__ da = &g_DA[b * 512];
        #pragma unroll 8
        for (int j = 0; j < 512; j++) acc += da[j] * g_tmp[j * EMB + c];
    }
    __shared__ float red[128];
    red[threadIdx.x] = (c < EMB) ? acc * acc : 0.f;
    __syncthreads();
    for (int off = 64; off > 0; off >>= 1) {
        if (threadIdx.x < off) red[threadIdx.x] += red[threadIdx.x + off];
        __syncthreads();
    }
    float inv = 1.0f / fmaxf(sqrtf(red[0]), 1e-12f);
    if (c < EMB) {
        float v = acc * inv;
        if (last) {
            out[b * EMB + c] = (g_accum[b * EMB + c] + v) * (1.0f / 3.0f);
        } else {
            g_sess[b * EMB + c]   = v;
            g_accum[b * EMB + c] += v;
        }
    }
}

// ---------------- launch --------------------------------------------------------
extern "C" void kernel_launch(void* const* d_in, const int* in_sizes, int n_in,
                              void* d_out, int out_size) {
    const float* emb   = (const float*)d_in[0];
    const float* vals  = (const float*)d_in[1];
    const int*   rows  = (const int*)d_in[2];
    const int*   cols  = (const int*)d_in[3];
    const float* D     = (const float*)d_in[4];
    const float* A     = (const float*)d_in[5];
    const int*   items = (const int*)d_in[6];
    const float* slen  = (const float*)d_in[7];
    const float* wsess = (const float*)d_in[8];
    float* out = (float*)d_out;

    (void)in_sizes; (void)n_in; (void)out_size;

    // CSR build + needed-row set
    k_zero<<<(N_NODE + 255) / 256, 256>>>();
    k_mark<<<(BATCH * SEQL + 255) / 256, 256>>>(items);
    k_count<<<(NNZ + 255) / 256, 256>>>(rows);
    k_scan1<<<SCAN_NB, SCAN_BLK>>>();
    k_scan2<<<1, 256>>>();
    k_scan3<<<(N_NODE + 255) / 256, 256>>>();
    k_scatter<<<(NNZ + 255) / 256, 256>>>(vals, rows, cols);

    // hyperconv
    const int spmm1_blocks = (N_NODE * 32 + 255) / 256;
    k_spmm1<<<spmm1_blocks, 256>>>(emb);
    const int spmm2_blocks = (MAXNEED * 32 + 255) / 256;
    k_spmm2<<<spmm2_blocks, 256>>>();

    // sessconv
    k_pool<<<BATCH, EMB>>>(emb, items, slen);
    k_mm512<<<dim3(16, 16), dim3(32, 32)>>>(D, A);

    k_linear<<<BATCH, EMB>>>(wsess + 0 * EMB * EMB);
    k_danorm<<<BATCH, 128>>>(0, out);
    k_linear<<<BATCH, EMB>>>(wsess + 1 * EMB * EMB);
    k_danorm<<<BATCH, 128>>>(1, out);
}